// round 7
// baseline (speedup 1.0000x reference)
#include <cuda_runtime.h>

// Row-wise softmax (no max subtraction): y = exp(x) / sum(exp(x), axis=-1)
// x: (16384, 4096) fp32.
// 1 CTA per row, 1024 threads, 4 elems/thread (1x float4).
// Endpoint of the oe*MLP_p1 trend (R1:32 -> R6:8 -> here:2): minimal
// front-batch burst per CTA, minimal live registers across the barrier.

#define COLS 4096
#define THREADS 1024

__global__ __launch_bounds__(THREADS, 2)
void softmax_row1024_kernel(const float4* __restrict__ x,
                            float4* __restrict__ y) {
    const int row = blockIdx.x;
    const size_t base = (size_t)row * (COLS / 4);
    const int tid = threadIdx.x;

    // Single vector load, exp in registers.
    float4 t = x[base + tid];
    t.x = __expf(t.x);
    t.y = __expf(t.y);
    t.z = __expf(t.z);
    t.w = __expf(t.w);
    float local = (t.x + t.y) + (t.z + t.w);

    // Block reduction: warp shuffle then 32 warp sums via smem broadcast.
    __shared__ float warp_sums[THREADS / 32];
#pragma unroll
    for (int o = 16; o > 0; o >>= 1)
        local += __shfl_xor_sync(0xFFFFFFFFu, local, o);
    if ((tid & 31) == 0)
        warp_sums[tid >> 5] = local;
    __syncthreads();

    float total = 0.0f;
#pragma unroll
    for (int w = 0; w < THREADS / 32; ++w)
        total += warp_sums[w];  // broadcast LDS, conflict-free

    const float inv = 1.0f / total;

    t.x *= inv;
    t.y *= inv;
    t.z *= inv;
    t.w *= inv;
    y[base + tid] = t;
}

extern "C" void kernel_launch(void* const* d_in, const int* in_sizes, int n_in,
                              void* d_out, int out_size) {
    const float4* x = (const float4*)d_in[0];
    float4* y = (float4*)d_out;
    const int rows = in_sizes[0] / COLS;  // 16384
    softmax_row1024_kernel<<<rows, THREADS>>>(x, y);
}

// round 8
// speedup vs baseline: 1.5056x; 1.5056x over previous
#include <cuda_runtime.h>

// Row-wise softmax (no max subtraction): y = exp(x) / sum(exp(x), axis=-1)
// x: (16384, 4096) fp32.
// Best measured geometry (R6, 80.99us wall): 1 CTA per row, 512 threads,
// 8 elems/thread (2x float4) in registers. Single change: stores are
// evict-first (.cs) so the never-re-read output stream doesn't churn L2
// against the read stream.

#define COLS 4096
#define THREADS 512
#define VPT 2   // 2 x float4 = 8 floats; 512*8 = 4096

__device__ __forceinline__ void stcs4(float4* p, float4 v) {
    asm volatile("st.global.cs.v4.f32 [%0], {%1,%2,%3,%4};"
                 :: "l"(p), "f"(v.x), "f"(v.y), "f"(v.z), "f"(v.w));
}

__global__ __launch_bounds__(THREADS, 4)
void softmax_row512_kernel(const float4* __restrict__ x,
                           float4* __restrict__ y) {
    const int row = blockIdx.x;
    const size_t base = (size_t)row * (COLS / 4);
    const float4* xr = x + base;
    float4* yr = y + base;
    const int tid = threadIdx.x;

    float4 v[VPT];
    float local = 0.0f;

    // Front-batched vector loads (MLP_p1 = 2), exp on the fly.
#pragma unroll
    for (int i = 0; i < VPT; ++i) {
        float4 t = xr[tid + i * THREADS];
        t.x = __expf(t.x);
        t.y = __expf(t.y);
        t.z = __expf(t.z);
        t.w = __expf(t.w);
        local += (t.x + t.y) + (t.z + t.w);
        v[i] = t;
    }

    // Block reduction: warp shuffle then 16 warp sums via smem broadcast.
    __shared__ float warp_sums[THREADS / 32];
#pragma unroll
    for (int o = 16; o > 0; o >>= 1)
        local += __shfl_xor_sync(0xFFFFFFFFu, local, o);
    if ((tid & 31) == 0)
        warp_sums[tid >> 5] = local;
    __syncthreads();

    float total = 0.0f;
#pragma unroll
    for (int w = 0; w < THREADS / 32; ++w)
        total += warp_sums[w];  // broadcast LDS, conflict-free

    const float inv = 1.0f / total;

#pragma unroll
    for (int i = 0; i < VPT; ++i) {
        float4 t = v[i];
        t.x *= inv;
        t.y *= inv;
        t.z *= inv;
        t.w *= inv;
        stcs4(yr + tid + i * THREADS, t);
    }
}

extern "C" void kernel_launch(void* const* d_in, const int* in_sizes, int n_in,
                              void* d_out, int out_size) {
    const float4* x = (const float4*)d_in[0];
    float4* y = (float4*)d_out;
    const int rows = in_sizes[0] / COLS;  // 16384
    softmax_row512_kernel<<<rows, THREADS>>>(x, y);
}